// round 13
// baseline (speedup 1.0000x reference)
#include <cuda_runtime.h>
#include <cuda_fp16.h>
#include <math.h>

#define N_MET   100000
#define N_RXN   200000
#define E_SUB   400000
#define E_PROD  400000
#define HIDDEN  128
#define MSG     64
#define DT      0.01f

#define SCAN_BS 512
#define NB1     ((N_RXN + SCAN_BS - 1) / SCAN_BS)   // 391

#define LDH 136     // smem stride (halves) for T and M tiles (conflict-free)
#define K2_TILE 64
#define K2_NTILES (N_RXN / K2_TILE)                 // 3125, exact
#define K2_GRID  296                                // 2 CTAs/SM, one wave
#define K2_THREADS 512
#define MAXE    256 // edge-staging chunk (per buffer)

#define HIST_B  ((E_SUB + 255) / 256)               // 1563
#define PROD_B  ((E_PROD + 255) / 256)              // 1563

// smem bytes: c1/V2/bb (1536) + cnt/ext (512) + P (1536) + E4 (8192)
//           + T half (64*LDH*2) + M half (128*LDH*2)
#define K2_SMEM_BYTES (1536 + 512 + 1536 + 2 * MAXE * 16 + K2_TILE * LDH * 2 + HIDDEN * LDH * 2)

// ---------------- scratch (device globals; no allocation allowed) -------------
// g_cnt and g_sstate start zero (BSS) and are re-zeroed at the graph tail each
// call, so every kernel_launch invocation sees the same initial state.
__device__ int                g_cnt[N_RXN];
__device__ unsigned long long g_sstate[NB1];        // lookback scan state
__device__ int                g_start[N_RXN];
__device__ int                g_cursor[N_RXN];
__device__ int                g_eidx[E_SUB];
__device__ __half             g_Mh[HIDDEN * HIDDEN];   // fp16 W2@V1, [n][k] layout
__device__ float              g_bb[HIDDEN];            // b2 @ V1
__device__ float              g_v[N_RXN];
__device__ float              g_vs[N_RXN];             // v * rxn_scale (folded)
__device__ float              g_totcons[N_MET];

#define ST_AGG (1ULL << 62)
#define ST_PRE (2ULL << 62)
#define ST_VAL 0x3FFFFFFFFFFFFFFFULL

__device__ __forceinline__ float tanh_fast(float x) {
    float y; asm("tanh.approx.f32 %0, %1;" : "=f"(y) : "f"(x)); return y;
}

// ---------------- L1: histogram + weight folding + zeroing (fused) ------------
__global__ void k_hist_init(const int*   __restrict__ rxn_sub,
                            const float* __restrict__ W2,
                            const float* __restrict__ V1,
                            const float* __restrict__ b2,
                            float* __restrict__ out)
{
    int blk = blockIdx.x, tid = threadIdx.x;
    if (blk < HIST_B) {
        int e = blk * 256 + tid;
        if (e < E_SUB) atomicAdd(&g_cnt[rxn_sub[e]], 1);
    } else if (blk < HIST_B + HIDDEN) {
        if (tid < HIDDEN) {
            int j = blk - HIST_B;   // k-dim index
            float acc = 0.f;
            for (int k = 0; k < MSG; k++)
                acc = fmaf(W2[j * MSG + k], V1[k * HIDDEN + tid], acc);
            g_Mh[tid * HIDDEN + j] = __float2half_rn(acc);   // [n][k] (B col-major)
        }
    } else if (blk == HIST_B + HIDDEN) {
        if (tid < HIDDEN) {
            float acc = 0.f;
            for (int k = 0; k < MSG; k++)
                acc = fmaf(b2[k], V1[k * HIDDEN + tid], acc);
            g_bb[tid] = acc;
        }
    } else {
        int i = (blk - (HIST_B + HIDDEN + 1)) * 256 + tid;
        int stride = (gridDim.x - (HIST_B + HIDDEN + 1)) * 256;
        for (int p = i; p < N_MET; p += stride) { g_totcons[p] = 0.f; out[p] = 0.f; }
    }
}

// ---------------- L2: single-pass decoupled-lookback exclusive scan -----------
__global__ void k_scan_lb() {
    __shared__ int s[SCAN_BS];
    __shared__ int s_running;
    int b = blockIdx.x, t = threadIdx.x;
    int i = b * SCAN_BS + t;
    int v = (i < N_RXN) ? g_cnt[i] : 0;
    s[t] = v; __syncthreads();
    for (int off = 1; off < SCAN_BS; off <<= 1) {
        int xx = (t >= off) ? s[t - off] : 0;
        __syncthreads();
        s[t] += xx;
        __syncthreads();
    }
    if (t == 0) {
        unsigned long long total = (unsigned long long)s[SCAN_BS - 1];
        if (b == 0) {
            atomicExch(&g_sstate[0], ST_PRE | total);
            s_running = 0;
        } else {
            atomicExch(&g_sstate[b], ST_AGG | total);
            unsigned long long run = 0;
            for (int pb = b - 1; pb >= 0; pb--) {
                unsigned long long st;
                do { st = atomicAdd(&g_sstate[pb], 0ULL); } while ((st >> 62) == 0ULL);
                run += st & ST_VAL;
                if ((st >> 62) == 2ULL) break;
            }
            atomicExch(&g_sstate[b], ST_PRE | (run + total));
            s_running = (int)run;
        }
    }
    __syncthreads();
    if (i < N_RXN) {
        int st = s_running + s[t] - v;
        g_start[i]  = st;
        g_cursor[i] = st;
    }
}

// ---------------- L3: scatter edge ids into CSR order -------------------------
__global__ void k_scatter(const int* __restrict__ rxn_sub) {
    int e = blockIdx.x * blockDim.x + threadIdx.x;
    if (e >= E_SUB) return;
    int pos = atomicAdd(&g_cursor[rxn_sub[e]], 1);
    g_eidx[pos] = e;
}

// ---------------- L4: persistent gather + layer1 + fp16 GEMM (R11 form) -------
__global__ __launch_bounds__(K2_THREADS, 2)
void k2_gemm(const float* __restrict__ x,
             const int*   __restrict__ met_sub,
             const float* __restrict__ sto_sub,
             const float* __restrict__ W1,
             const float* __restrict__ b1,
             const float* __restrict__ c1v,
             const float* __restrict__ V2,
             const float* __restrict__ c2,
             const float* __restrict__ log_k)
{
    extern __shared__ float sm[];
    float*    sc1  = sm;                               // 128
    float*    sV2  = sc1 + 128;                        // 128
    float*    sbb  = sV2 + 128;                        // 128
    float*    scnt = sbb + 128;                        // 64
    float*    sext = scnt + 64;                        // 64
    float*    sP   = sext + 64;                        // 384 (3 partial sets)
    float4*   sE4  = (float4*)(sP + 384);              // 2 x MAXE float4
    __half*   sTh  = (__half*)(sE4 + 2 * MAXE);        // 64 x LDH halves
    __half*   sMh  = sTh + K2_TILE * LDH;              // 128 x LDH halves

    int tid = threadIdx.x;
    int w = tid >> 5, lane = tid & 31, gid = lane >> 2, tig = lane & 3;
    int wr = w & 3;                                    // row-group for mma
    int s_set = w >> 2;                                // nt quarter 0..3
    int nt0 = s_set * 4;

    // stage weights & biases ONCE per block
    if (tid < 128) {
        sc1[tid] = c1v[tid];
        sV2[tid] = V2[tid];
        sbb[tid] = g_bb[tid];
    }
    for (int i = tid; i < HIDDEN * HIDDEN / 2; i += K2_THREADS) {
        int row = i >> 6, col2 = i & 63;               // 64 half2 per row
        reinterpret_cast<__half2*>(sMh)[row * (LDH / 2) + col2] =
            reinterpret_cast<const __half2*>(g_Mh)[i];
    }
    float c2s = c2[0];

    // per-lane register weights: units 4*lane .. 4*lane+3
    float4 u4 = reinterpret_cast<const float4*>(W1)[lane];
    float4 w4 = reinterpret_cast<const float4*>(W1 + HIDDEN)[lane];
    float4 b4 = reinterpret_cast<const float4*>(b1)[lane];

    // prologue: stage first tile's edges into buffer 0
    int pb = 0;
    {
        int rf = blockIdx.x * K2_TILE;
        int eb = g_start[rf];
        int te = g_start[rf + K2_TILE - 1] + g_cnt[rf + K2_TILE - 1] - eb;
        int ch = min(te, MAXE);
        for (int i = tid; i < ch; i += K2_THREADS) {
            int idx = g_eidx[eb + i];
            int met = met_sub[idx];
            sE4[i] = make_float4(x[met * 8 + 3], sto_sub[idx], x[met * 8 + 4], 0.f);
        }
    }

    for (int tile = blockIdx.x; tile < K2_NTILES; tile += K2_GRID) {
        int r_first = tile * K2_TILE;
        int e_begin = g_start[r_first];
        int last    = r_first + K2_TILE - 1;
        int totE    = g_start[last] + g_cnt[last] - e_begin;

        // row descriptors for this warp's 4 rows
        int rb = r_first + 4 * w;
        int s0 = g_start[rb + 0] - e_begin, c0 = g_cnt[rb + 0];
        int s1 = g_start[rb + 1] - e_begin, c1 = g_cnt[rb + 1];
        int s2 = g_start[rb + 2] - e_begin, c2n = g_cnt[rb + 2];
        int s3 = g_start[rb + 3] - e_begin, c3 = g_cnt[rb + 3];

        float4* sEcur = sE4 + pb * MAXE;

        float acc00=0.f,acc01=0.f,acc02=0.f,acc03=0.f;
        float acc10=0.f,acc11=0.f,acc12=0.f,acc13=0.f;
        float acc20=0.f,acc21=0.f,acc22=0.f,acc23=0.f;
        float acc30=0.f,acc31=0.f,acc32=0.f,acc33=0.f;
        float ext0=0.f, ext1=0.f, ext2=0.f, ext3=0.f;

        __syncthreads();   // prefetched sE ready; sT/sP from prev tile released

        for (int base = 0; base < totE; base += MAXE) {
            int ch = min(MAXE, totE - base);
            if (base > 0) {   // rare slow path: restage into own buffer
                __syncthreads();
                for (int i = tid; i < ch; i += K2_THREADS) {
                    int idx = g_eidx[e_begin + base + i];
                    int met = met_sub[idx];
                    sEcur[i] = make_float4(x[met * 8 + 3], sto_sub[idx], x[met * 8 + 4], 0.f);
                }
                __syncthreads();
            }
            #define ROW_LOOP(RR, SR, CN) { \
                int lo = max(SR, base), hi = min(SR + CN, base + ch); \
                for (int l = lo; l < hi; l++) { \
                    float4 e = sEcur[l - base]; \
                    ext##RR += e.z; \
                    acc##RR##0 += tanh_fast(fmaf(e.x, u4.x, fmaf(e.y, w4.x, b4.x))); \
                    acc##RR##1 += tanh_fast(fmaf(e.x, u4.y, fmaf(e.y, w4.y, b4.y))); \
                    acc##RR##2 += tanh_fast(fmaf(e.x, u4.z, fmaf(e.y, w4.z, b4.z))); \
                    acc##RR##3 += tanh_fast(fmaf(e.x, u4.w, fmaf(e.y, w4.w, b4.w))); \
                } }
            ROW_LOOP(0, s0, c0)
            ROW_LOOP(1, s1, c1)
            ROW_LOOP(2, s2, c2n)
            ROW_LOOP(3, s3, c3)
            #undef ROW_LOOP
        }

        // write T tile as fp16: lane l -> units 4l..4l+3 (two half2 = 8 bytes)
        #define ST_ROW(RR) { \
            __half2 h0 = __floats2half2_rn(acc##RR##0, acc##RR##1); \
            __half2 h1 = __floats2half2_rn(acc##RR##2, acc##RR##3); \
            *reinterpret_cast<__half2*>(&sTh[(4 * w + RR) * LDH + 4 * lane])     = h0; \
            *reinterpret_cast<__half2*>(&sTh[(4 * w + RR) * LDH + 4 * lane + 2]) = h1; }
        ST_ROW(0) ST_ROW(1) ST_ROW(2) ST_ROW(3)
        #undef ST_ROW
        if (lane == 0) {
            scnt[4 * w + 0] = (float)c0;  sext[4 * w + 0] = ext0;
            scnt[4 * w + 1] = (float)c1;  sext[4 * w + 1] = ext1;
            scnt[4 * w + 2] = (float)c2n; sext[4 * w + 2] = ext2;
            scnt[4 * w + 3] = (float)c3;  sext[4 * w + 3] = ext3;
        }
        __syncthreads();

        // prefetch next tile's edges into alternate buffer (overlaps with mma)
        int tnext = tile + K2_GRID;
        if (tnext < K2_NTILES) {
            float4* sEnx = sE4 + (pb ^ 1) * MAXE;
            int rf2 = tnext * K2_TILE;
            int eb2 = g_start[rf2];
            int te2 = g_start[rf2 + K2_TILE - 1] + g_cnt[rf2 + K2_TILE - 1] - eb2;
            int ch2 = min(te2, MAXE);
            for (int i = tid; i < ch2; i += K2_THREADS) {
                int idx = g_eidx[eb2 + i];
                int met = met_sub[idx];
                sEnx[i] = make_float4(x[met * 8 + 3], sto_sub[idx], x[met * 8 + 4], 0.f);
            }
        }

        // ---- mma: fp16 m16n8k16, 8 k-steps, 4 nt-tiles per warp ----
        float accm[4][4];
        #pragma unroll
        for (int j = 0; j < 4; j++) {
            accm[j][0] = 0.f; accm[j][1] = 0.f; accm[j][2] = 0.f; accm[j][3] = 0.f;
        }

        #pragma unroll
        for (int kt = 0; kt < 8; kt++) {
            int k = kt * 16;
            int ra = (wr * 16 + gid) * LDH, rb2 = (wr * 16 + gid + 8) * LDH;
            unsigned a0 = *reinterpret_cast<const unsigned*>(&sTh[ra  + k + 2 * tig]);
            unsigned a1 = *reinterpret_cast<const unsigned*>(&sTh[rb2 + k + 2 * tig]);
            unsigned a2 = *reinterpret_cast<const unsigned*>(&sTh[ra  + k + 8 + 2 * tig]);
            unsigned a3 = *reinterpret_cast<const unsigned*>(&sTh[rb2 + k + 8 + 2 * tig]);
            #pragma unroll
            for (int j = 0; j < 4; j++) {
                int n0 = (nt0 + j) * 8;
                const __half* mcol = sMh + (n0 + gid) * LDH + k;
                unsigned b0 = *reinterpret_cast<const unsigned*>(mcol + 2 * tig);
                unsigned b1 = *reinterpret_cast<const unsigned*>(mcol + 8 + 2 * tig);
                asm volatile(
                    "mma.sync.aligned.m16n8k16.row.col.f32.f16.f16.f32 "
                    "{%0,%1,%2,%3}, {%4,%5,%6,%7}, {%8,%9}, {%0,%1,%2,%3};"
                    : "+f"(accm[j][0]), "+f"(accm[j][1]), "+f"(accm[j][2]), "+f"(accm[j][3])
                    : "r"(a0), "r"(a1), "r"(a2), "r"(a3), "r"(b0), "r"(b1));
            }
        }

        float cnt0 = scnt[wr * 16 + gid], cnt1 = scnt[wr * 16 + gid + 8];
        float acc0 = 0.f, acc1 = 0.f;
        #pragma unroll
        for (int j = 0; j < 4; j++) {
            int n0 = (nt0 + j) * 8;
            int col0 = n0 + 2 * tig, col1 = col0 + 1;
            float bi0 = sc1[col0], bi1 = sc1[col1];
            float bb0 = sbb[col0], bb1 = sbb[col1];
            float v0  = sV2[col0], v1  = sV2[col1];
            acc0 += tanh_fast(fmaf(cnt0, bb0, accm[j][0]) + bi0) * v0
                  + tanh_fast(fmaf(cnt0, bb1, accm[j][1]) + bi1) * v1;
            acc1 += tanh_fast(fmaf(cnt1, bb0, accm[j][2]) + bi0) * v0
                  + tanh_fast(fmaf(cnt1, bb1, accm[j][3]) + bi1) * v1;
        }

        acc0 += __shfl_xor_sync(0xffffffffu, acc0, 1);
        acc0 += __shfl_xor_sync(0xffffffffu, acc0, 2);
        acc1 += __shfl_xor_sync(0xffffffffu, acc1, 1);
        acc1 += __shfl_xor_sync(0xffffffffu, acc1, 2);

        if (s_set > 0 && tig == 0) {
            sP[(s_set - 1) * 128 + wr * 16 + gid]     = acc0;
            sP[(s_set - 1) * 128 + wr * 16 + gid + 8] = acc1;
        }
        __syncthreads();

        if (s_set == 0 && tig == 0) {
            int i0 = wr * 16 + gid;
            acc0 += sP[i0] + sP[128 + i0] + sP[256 + i0];
            acc1 += sP[i0 + 8] + sP[128 + i0 + 8] + sP[256 + i0 + 8];
            int r0 = r_first + i0;
            {
                float z    = acc0 + c2s;
                float base = fmaxf(z, 0.f) + log1pf(expf(-fabsf(z)));
                float extm = sext[i0] / fmaxf(scnt[i0], 1.f);
                g_v[r0] = exp10f(log_k[r0]) * extm * base;
            }
            int r1 = r0 + 8;
            {
                float z    = acc1 + c2s;
                float base = fmaxf(z, 0.f) + log1pf(expf(-fabsf(z)));
                float extm = sext[i0 + 8] / fmaxf(scnt[i0 + 8], 1.f);
                g_v[r1] = exp10f(log_k[r1]) * extm * base;
            }
        }

        pb ^= 1;
    }
}

// ---------------- L5: total consumption per metabolite (edge-parallel) --------
__global__ void k_totcons(const int* __restrict__ met_sub,
                          const int* __restrict__ rxn_sub,
                          const float* __restrict__ sto_sub)
{
    int e = blockIdx.x * blockDim.x + threadIdx.x;
    if (e >= E_SUB) return;
    float c = sto_sub[e] * g_v[rxn_sub[e]] * DT;
    atomicAdd(&g_totcons[met_sub[e]], c);
}

// ---------------- L6: CSR rscale + fold v*scale + sub contributions -----------
// One thread per reaction: local min over its edges (no atomicMin), then
// scatters the sub-edge contributions with the folded rate.
__global__ void k_rscale_csr(const float* __restrict__ x,
                             const int*   __restrict__ met_sub,
                             const float* __restrict__ sto_sub,
                             float* __restrict__ out)
{
    int r = blockIdx.x * blockDim.x + threadIdx.x;
    if (r >= N_RXN) return;
    int s = g_start[r], c = g_cnt[r];
    float mn = 1.f;
    for (int l = 0; l < c; l++) {
        int idx = g_eidx[s + l];
        int m = met_sub[idx];
        float tot  = g_totcons[m];
        float conc = x[m * 8 + 3];
        float sc = (tot > 1e-12f) ? fminf(conc / tot, 1.0f) : 1.0f;
        mn = fminf(mn, sc);
    }
    float vs = g_v[r] * mn;
    g_vs[r] = vs;
    for (int l = 0; l < c; l++) {
        int idx = g_eidx[s + l];
        atomicAdd(&out[met_sub[idx]], -sto_sub[idx] * vs);
    }
}

// ---------------- L7: product contributions + tail re-zero --------------------
__global__ void k_contrib_prod(const int* __restrict__ met_prod,
                               const int* __restrict__ rxn_prod,
                               const float* __restrict__ sto_prod,
                               float* __restrict__ out)
{
    int blk = blockIdx.x, tid = threadIdx.x;
    if (blk < PROD_B) {
        int e = blk * 256 + tid;
        if (e >= E_PROD) return;
        atomicAdd(&out[met_prod[e]], sto_prod[e] * g_vs[rxn_prod[e]]);
    } else {
        // restore zero-state invariant for the next invocation
        int i = (blk - PROD_B) * 256 + tid;
        int stride = (gridDim.x - PROD_B) * 256;
        for (int p = i; p < N_RXN; p += stride) g_cnt[p] = 0;
        for (int p = i; p < NB1; p += stride) g_sstate[p] = 0ULL;
    }
}

// ---------------- launch ------------------------------------------------------
extern "C" void kernel_launch(void* const* d_in, const int* in_sizes, int n_in,
                              void* d_out, int out_size)
{
    const float* x        = (const float*)d_in[0];
    const int*   met_sub  = (const int*)  d_in[1];
    const int*   rxn_sub  = (const int*)  d_in[2];
    const float* sto_sub  = (const float*)d_in[3];
    const int*   met_prod = (const int*)  d_in[4];
    const int*   rxn_prod = (const int*)  d_in[5];
    const float* sto_prod = (const float*)d_in[6];
    const float* W1       = (const float*)d_in[7];
    const float* b1       = (const float*)d_in[8];
    const float* W2       = (const float*)d_in[9];
    const float* b2       = (const float*)d_in[10];
    const float* V1       = (const float*)d_in[11];
    const float* c1       = (const float*)d_in[12];
    const float* V2       = (const float*)d_in[13];
    const float* c2       = (const float*)d_in[14];
    const float* log_k    = (const float*)d_in[15];
    float* out = (float*)d_out;

    cudaFuncSetAttribute(k2_gemm, cudaFuncAttributeMaxDynamicSharedMemorySize,
                         K2_SMEM_BYTES);

    // 1: histogram + weight fold + zero(out, totcons)
    k_hist_init<<<HIST_B + HIDDEN + 1 + 256, 256>>>(rxn_sub, W2, V1, b2, out);
    // 2: single-pass scan -> g_start, g_cursor
    k_scan_lb<<<NB1, SCAN_BS>>>();
    // 3: CSR scatter
    k_scatter<<<(E_SUB + 255) / 256, 256>>>(rxn_sub);
    // 4: the big fused kernel (profiled slot)
    k2_gemm<<<K2_GRID, K2_THREADS, K2_SMEM_BYTES>>>(x, met_sub, sto_sub,
                                                    W1, b1, c1, V2, c2, log_k);
    // 5: total consumption
    k_totcons<<<(E_SUB + 255) / 256, 256>>>(met_sub, rxn_sub, sto_sub);
    // 6: per-rxn min scale + fold + sub contributions (CSR)
    k_rscale_csr<<<(N_RXN + 255) / 256, 256>>>(x, met_sub, sto_sub, out);
    // 7: product contributions + tail zero
    k_contrib_prod<<<PROD_B + 128, 256>>>(met_prod, rxn_prod, sto_prod, out);
}

// round 14
// speedup vs baseline: 1.0691x; 1.0691x over previous
#include <cuda_runtime.h>
#include <cuda_fp16.h>
#include <math.h>

#define N_MET   100000
#define N_RXN   200000
#define E_SUB   400000
#define E_PROD  400000
#define HIDDEN  128
#define MSG     64
#define DT      0.01f

#define SCAN_BS 512
#define NB1     ((N_RXN + SCAN_BS - 1) / SCAN_BS)   // 391

#define LDH 136     // smem stride (halves) for T and M tiles (conflict-free)
#define K2_TILE 64
#define K2_NTILES (N_RXN / K2_TILE)                 // 3125, exact
#define K2_GRID  296                                // 2 CTAs/SM, one wave
#define K2_THREADS 512
#define MAXE    256 // edge-staging chunk (per buffer)

#define HIST_B    ((E_SUB + 255) / 256)             // 1563
#define CONTRIB_B ((E_SUB + E_PROD + 255) / 256)    // 3125

// smem bytes: c1/V2/bb (1536) + cnt/ext (512) + P (1536) + E4 (8192)
//           + T half (64*LDH*2) + M half (128*LDH*2)
#define K2_SMEM_BYTES (1536 + 512 + 1536 + 2 * MAXE * 16 + K2_TILE * LDH * 2 + HIDDEN * LDH * 2)

// ---------------- scratch (device globals; no allocation allowed) -------------
// g_cnt and g_sstate start zero (BSS) and are re-zeroed at the graph tail each
// call, so every kernel_launch invocation sees the same initial state.
__device__ int                g_cnt[N_RXN];
__device__ unsigned long long g_sstate[NB1];        // lookback scan state
__device__ int                g_start[N_RXN];
__device__ int                g_cursor[N_RXN];
__device__ int                g_eidx[E_SUB];
__device__ __half             g_Mh[HIDDEN * HIDDEN];   // fp16 W2@V1, [n][k] layout
__device__ float              g_bb[HIDDEN];            // b2 @ V1
__device__ float              g_v[N_RXN];
__device__ float              g_rscale[N_RXN];
__device__ float              g_totcons[N_MET];

#define ST_AGG (1ULL << 62)
#define ST_PRE (2ULL << 62)
#define ST_VAL 0x3FFFFFFFFFFFFFFFULL

__device__ __forceinline__ float tanh_fast(float x) {
    float y; asm("tanh.approx.f32 %0, %1;" : "=f"(y) : "f"(x)); return y;
}
__device__ __forceinline__ unsigned smem_u32(const void* p) {
    return (unsigned)__cvta_generic_to_shared(p);
}
#define LDSM_X4(r0, r1, r2, r3, addr) \
    asm volatile("ldmatrix.sync.aligned.m8n8.x4.shared.b16 {%0,%1,%2,%3}, [%4];" \
                 : "=r"(r0), "=r"(r1), "=r"(r2), "=r"(r3) : "r"(addr))
#define LDSM_X2(r0, r1, addr) \
    asm volatile("ldmatrix.sync.aligned.m8n8.x2.shared.b16 {%0,%1}, [%2];" \
                 : "=r"(r0), "=r"(r1) : "r"(addr))

// ---------------- L1: histogram + weight folding + zeroing (fused) ------------
__global__ void k_hist_init(const int*   __restrict__ rxn_sub,
                            const float* __restrict__ W2,
                            const float* __restrict__ V1,
                            const float* __restrict__ b2,
                            float* __restrict__ out)
{
    int blk = blockIdx.x, tid = threadIdx.x;
    if (blk < HIST_B) {
        int e = blk * 256 + tid;
        if (e < E_SUB) atomicAdd(&g_cnt[rxn_sub[e]], 1);
    } else if (blk < HIST_B + HIDDEN) {
        if (tid < HIDDEN) {
            int j = blk - HIST_B;   // k-dim index
            float acc = 0.f;
            for (int k = 0; k < MSG; k++)
                acc = fmaf(W2[j * MSG + k], V1[k * HIDDEN + tid], acc);
            g_Mh[tid * HIDDEN + j] = __float2half_rn(acc);   // [n][k] (B col-major)
        }
    } else if (blk == HIST_B + HIDDEN) {
        if (tid < HIDDEN) {
            float acc = 0.f;
            for (int k = 0; k < MSG; k++)
                acc = fmaf(b2[k], V1[k * HIDDEN + tid], acc);
            g_bb[tid] = acc;
        }
    } else {
        int i = (blk - (HIST_B + HIDDEN + 1)) * 256 + tid;
        int stride = (gridDim.x - (HIST_B + HIDDEN + 1)) * 256;
        for (int p = i; p < N_MET; p += stride) { g_totcons[p] = 0.f; out[p] = 0.f; }
    }
}

// ---------------- L2: single-pass decoupled-lookback exclusive scan -----------
__global__ void k_scan_lb() {
    __shared__ int s[SCAN_BS];
    __shared__ int s_running;
    int b = blockIdx.x, t = threadIdx.x;
    int i = b * SCAN_BS + t;
    int v = (i < N_RXN) ? g_cnt[i] : 0;
    s[t] = v; __syncthreads();
    for (int off = 1; off < SCAN_BS; off <<= 1) {
        int xx = (t >= off) ? s[t - off] : 0;
        __syncthreads();
        s[t] += xx;
        __syncthreads();
    }
    if (t == 0) {
        unsigned long long total = (unsigned long long)s[SCAN_BS - 1];
        if (b == 0) {
            atomicExch(&g_sstate[0], ST_PRE | total);
            s_running = 0;
        } else {
            atomicExch(&g_sstate[b], ST_AGG | total);
            unsigned long long run = 0;
            for (int pb = b - 1; pb >= 0; pb--) {
                unsigned long long st;
                do { st = atomicAdd(&g_sstate[pb], 0ULL); } while ((st >> 62) == 0ULL);
                run += st & ST_VAL;
                if ((st >> 62) == 2ULL) break;
            }
            atomicExch(&g_sstate[b], ST_PRE | (run + total));
            s_running = (int)run;
        }
    }
    __syncthreads();
    if (i < N_RXN) {
        int st = s_running + s[t] - v;
        g_start[i]  = st;
        g_cursor[i] = st;
    }
}

// ---------------- L3: scatter edge ids into CSR order -------------------------
__global__ void k_scatter(const int* __restrict__ rxn_sub) {
    int e = blockIdx.x * blockDim.x + threadIdx.x;
    if (e >= E_SUB) return;
    int pos = atomicAdd(&g_cursor[rxn_sub[e]], 1);
    g_eidx[pos] = e;
}

// ---------------- L4: persistent gather + layer1 + fp16 GEMM (ldmatrix) -------
__global__ __launch_bounds__(K2_THREADS, 2)
void k2_gemm(const float* __restrict__ x,
             const int*   __restrict__ met_sub,
             const float* __restrict__ sto_sub,
             const float* __restrict__ W1,
             const float* __restrict__ b1,
             const float* __restrict__ c1v,
             const float* __restrict__ V2,
             const float* __restrict__ c2,
             const float* __restrict__ log_k)
{
    extern __shared__ float sm[];
    float*    sc1  = sm;                               // 128
    float*    sV2  = sc1 + 128;                        // 128
    float*    sbb  = sV2 + 128;                        // 128
    float*    scnt = sbb + 128;                        // 64
    float*    sext = scnt + 64;                        // 64
    float*    sP   = sext + 64;                        // 384 (3 partial sets)
    float4*   sE4  = (float4*)(sP + 384);              // 2 x MAXE float4
    __half*   sTh  = (__half*)(sE4 + 2 * MAXE);        // 64 x LDH halves
    __half*   sMh  = sTh + K2_TILE * LDH;              // 128 x LDH halves

    int tid = threadIdx.x;
    int w = tid >> 5, lane = tid & 31, gid = lane >> 2, tig = lane & 3;
    int wr = w & 3;                                    // row-group for mma
    int s_set = w >> 2;                                // nt quarter 0..3
    int nt0 = s_set * 4;

    // stage weights & biases ONCE per block
    if (tid < 128) {
        sc1[tid] = c1v[tid];
        sV2[tid] = V2[tid];
        sbb[tid] = g_bb[tid];
    }
    for (int i = tid; i < HIDDEN * HIDDEN / 2; i += K2_THREADS) {
        int row = i >> 6, col2 = i & 63;               // 64 half2 per row
        reinterpret_cast<__half2*>(sMh)[row * (LDH / 2) + col2] =
            reinterpret_cast<const __half2*>(g_Mh)[i];
    }
    float c2s = c2[0];

    // per-lane register weights: units 4*lane .. 4*lane+3
    float4 u4 = reinterpret_cast<const float4*>(W1)[lane];
    float4 w4 = reinterpret_cast<const float4*>(W1 + HIDDEN)[lane];
    float4 b4 = reinterpret_cast<const float4*>(b1)[lane];

    // ldmatrix base addresses (constant across tiles)
    // A (x4): lanes 0-7 -> rows 0-7 k-low, 8-15 -> rows 8-15 k-low,
    //         16-23 -> rows 0-7 k-high, 24-31 -> rows 8-15 k-high
    unsigned aaddr = smem_u32(sTh) +
        (((wr * 16 + (lane & 15)) * LDH + 8 * (lane >> 4)) << 1);
    // B (x2) per nt-tile j: lanes 0-7 -> rows n0..n0+7 k-low, 8-15 -> k-high
    unsigned baddr[4];
    #pragma unroll
    for (int j = 0; j < 4; j++)
        baddr[j] = smem_u32(sMh) +
            ((((nt0 + j) * 8 + (lane & 7)) * LDH + 8 * ((lane >> 3) & 1)) << 1);

    // prologue: stage first tile's edges into buffer 0
    int pb = 0;
    {
        int rf = blockIdx.x * K2_TILE;
        int eb = g_start[rf];
        int te = g_start[rf + K2_TILE - 1] + g_cnt[rf + K2_TILE - 1] - eb;
        int ch = min(te, MAXE);
        for (int i = tid; i < ch; i += K2_THREADS) {
            int idx = g_eidx[eb + i];
            int met = met_sub[idx];
            sE4[i] = make_float4(x[met * 8 + 3], sto_sub[idx], x[met * 8 + 4], 0.f);
        }
    }

    for (int tile = blockIdx.x; tile < K2_NTILES; tile += K2_GRID) {
        int r_first = tile * K2_TILE;
        int e_begin = g_start[r_first];
        int last    = r_first + K2_TILE - 1;
        int totE    = g_start[last] + g_cnt[last] - e_begin;

        // row descriptors for this warp's 4 rows
        int rb = r_first + 4 * w;
        int s0 = g_start[rb + 0] - e_begin, c0 = g_cnt[rb + 0];
        int s1 = g_start[rb + 1] - e_begin, c1 = g_cnt[rb + 1];
        int s2 = g_start[rb + 2] - e_begin, c2n = g_cnt[rb + 2];
        int s3 = g_start[rb + 3] - e_begin, c3 = g_cnt[rb + 3];

        float4* sEcur = sE4 + pb * MAXE;

        float acc00=0.f,acc01=0.f,acc02=0.f,acc03=0.f;
        float acc10=0.f,acc11=0.f,acc12=0.f,acc13=0.f;
        float acc20=0.f,acc21=0.f,acc22=0.f,acc23=0.f;
        float acc30=0.f,acc31=0.f,acc32=0.f,acc33=0.f;
        float ext0=0.f, ext1=0.f, ext2=0.f, ext3=0.f;

        __syncthreads();   // prefetched sE ready; sT/sP from prev tile released

        for (int base = 0; base < totE; base += MAXE) {
            int ch = min(MAXE, totE - base);
            if (base > 0) {   // rare slow path: restage into own buffer
                __syncthreads();
                for (int i = tid; i < ch; i += K2_THREADS) {
                    int idx = g_eidx[e_begin + base + i];
                    int met = met_sub[idx];
                    sEcur[i] = make_float4(x[met * 8 + 3], sto_sub[idx], x[met * 8 + 4], 0.f);
                }
                __syncthreads();
            }
            #define ROW_LOOP(RR, SR, CN) { \
                int lo = max(SR, base), hi = min(SR + CN, base + ch); \
                for (int l = lo; l < hi; l++) { \
                    float4 e = sEcur[l - base]; \
                    ext##RR += e.z; \
                    acc##RR##0 += tanh_fast(fmaf(e.x, u4.x, fmaf(e.y, w4.x, b4.x))); \
                    acc##RR##1 += tanh_fast(fmaf(e.x, u4.y, fmaf(e.y, w4.y, b4.y))); \
                    acc##RR##2 += tanh_fast(fmaf(e.x, u4.z, fmaf(e.y, w4.z, b4.z))); \
                    acc##RR##3 += tanh_fast(fmaf(e.x, u4.w, fmaf(e.y, w4.w, b4.w))); \
                } }
            ROW_LOOP(0, s0, c0)
            ROW_LOOP(1, s1, c1)
            ROW_LOOP(2, s2, c2n)
            ROW_LOOP(3, s3, c3)
            #undef ROW_LOOP
        }

        // write T tile as fp16: lane l -> units 4l..4l+3 (two half2 = 8 bytes)
        #define ST_ROW(RR) { \
            __half2 h0 = __floats2half2_rn(acc##RR##0, acc##RR##1); \
            __half2 h1 = __floats2half2_rn(acc##RR##2, acc##RR##3); \
            *reinterpret_cast<__half2*>(&sTh[(4 * w + RR) * LDH + 4 * lane])     = h0; \
            *reinterpret_cast<__half2*>(&sTh[(4 * w + RR) * LDH + 4 * lane + 2]) = h1; }
        ST_ROW(0) ST_ROW(1) ST_ROW(2) ST_ROW(3)
        #undef ST_ROW
        if (lane == 0) {
            scnt[4 * w + 0] = (float)c0;  sext[4 * w + 0] = ext0;
            scnt[4 * w + 1] = (float)c1;  sext[4 * w + 1] = ext1;
            scnt[4 * w + 2] = (float)c2n; sext[4 * w + 2] = ext2;
            scnt[4 * w + 3] = (float)c3;  sext[4 * w + 3] = ext3;
        }
        __syncthreads();

        // prefetch next tile's edges into alternate buffer (overlaps with mma)
        int tnext = tile + K2_GRID;
        if (tnext < K2_NTILES) {
            float4* sEnx = sE4 + (pb ^ 1) * MAXE;
            int rf2 = tnext * K2_TILE;
            int eb2 = g_start[rf2];
            int te2 = g_start[rf2 + K2_TILE - 1] + g_cnt[rf2 + K2_TILE - 1] - eb2;
            int ch2 = min(te2, MAXE);
            for (int i = tid; i < ch2; i += K2_THREADS) {
                int idx = g_eidx[eb2 + i];
                int met = met_sub[idx];
                sEnx[i] = make_float4(x[met * 8 + 3], sto_sub[idx], x[met * 8 + 4], 0.f);
            }
        }

        // ---- mma: fp16 m16n8k16, ldmatrix operands, 4 nt-tiles per warp ----
        float accm[4][4];
        #pragma unroll
        for (int j = 0; j < 4; j++) {
            accm[j][0] = 0.f; accm[j][1] = 0.f; accm[j][2] = 0.f; accm[j][3] = 0.f;
        }

        #pragma unroll
        for (int kt = 0; kt < 8; kt++) {
            unsigned koff = kt * 32;                   // 16 halves = 32 bytes
            unsigned a0, a1, a2, a3;
            LDSM_X4(a0, a1, a2, a3, aaddr + koff);
            #pragma unroll
            for (int j = 0; j < 4; j++) {
                unsigned b0, b1;
                LDSM_X2(b0, b1, baddr[j] + koff);
                asm volatile(
                    "mma.sync.aligned.m16n8k16.row.col.f32.f16.f16.f32 "
                    "{%0,%1,%2,%3}, {%4,%5,%6,%7}, {%8,%9}, {%0,%1,%2,%3};"
                    : "+f"(accm[j][0]), "+f"(accm[j][1]), "+f"(accm[j][2]), "+f"(accm[j][3])
                    : "r"(a0), "r"(a1), "r"(a2), "r"(a3), "r"(b0), "r"(b1));
            }
        }

        float cnt0 = scnt[wr * 16 + gid], cnt1 = scnt[wr * 16 + gid + 8];
        float acc0 = 0.f, acc1 = 0.f;
        #pragma unroll
        for (int j = 0; j < 4; j++) {
            int n0 = (nt0 + j) * 8;
            int col0 = n0 + 2 * tig, col1 = col0 + 1;
            float bi0 = sc1[col0], bi1 = sc1[col1];
            float bb0 = sbb[col0], bb1 = sbb[col1];
            float v0  = sV2[col0], v1  = sV2[col1];
            acc0 += tanh_fast(fmaf(cnt0, bb0, accm[j][0]) + bi0) * v0
                  + tanh_fast(fmaf(cnt0, bb1, accm[j][1]) + bi1) * v1;
            acc1 += tanh_fast(fmaf(cnt1, bb0, accm[j][2]) + bi0) * v0
                  + tanh_fast(fmaf(cnt1, bb1, accm[j][3]) + bi1) * v1;
        }

        acc0 += __shfl_xor_sync(0xffffffffu, acc0, 1);
        acc0 += __shfl_xor_sync(0xffffffffu, acc0, 2);
        acc1 += __shfl_xor_sync(0xffffffffu, acc1, 1);
        acc1 += __shfl_xor_sync(0xffffffffu, acc1, 2);

        if (s_set > 0 && tig == 0) {
            sP[(s_set - 1) * 128 + wr * 16 + gid]     = acc0;
            sP[(s_set - 1) * 128 + wr * 16 + gid + 8] = acc1;
        }
        __syncthreads();

        if (s_set == 0 && tig == 0) {
            int i0 = wr * 16 + gid;
            acc0 += sP[i0] + sP[128 + i0] + sP[256 + i0];
            acc1 += sP[i0 + 8] + sP[128 + i0 + 8] + sP[256 + i0 + 8];
            int r0 = r_first + i0;
            {
                float z    = acc0 + c2s;
                float base = fmaxf(z, 0.f) + log1pf(expf(-fabsf(z)));
                float extm = sext[i0] / fmaxf(scnt[i0], 1.f);
                g_v[r0]      = exp10f(log_k[r0]) * extm * base;
                g_rscale[r0] = 1.f;
            }
            int r1 = r0 + 8;
            {
                float z    = acc1 + c2s;
                float base = fmaxf(z, 0.f) + log1pf(expf(-fabsf(z)));
                float extm = sext[i0 + 8] / fmaxf(scnt[i0 + 8], 1.f);
                g_v[r1]      = exp10f(log_k[r1]) * extm * base;
                g_rscale[r1] = 1.f;
            }
        }

        pb ^= 1;
    }
}

// ---------------- L5: total consumption per metabolite (edge-parallel) --------
__global__ void k_totcons(const int* __restrict__ met_sub,
                          const int* __restrict__ rxn_sub,
                          const float* __restrict__ sto_sub)
{
    int e = blockIdx.x * blockDim.x + threadIdx.x;
    if (e >= E_SUB) return;
    float c = sto_sub[e] * g_v[rxn_sub[e]] * DT;
    atomicAdd(&g_totcons[met_sub[e]], c);
}

// ---------------- L6: per-rxn min scale (edge-parallel atomicMin) -------------
__global__ void k_rscale(const float* __restrict__ x,
                         const int* __restrict__ met_sub,
                         const int* __restrict__ rxn_sub)
{
    int e = blockIdx.x * blockDim.x + threadIdx.x;
    if (e >= E_SUB) return;
    int   m    = met_sub[e];
    float tot  = g_totcons[m];
    float conc = x[m * 8 + 3];
    float sc   = (tot > 1e-12f) ? fminf(conc / tot, 1.0f) : 1.0f;
    atomicMin(reinterpret_cast<int*>(&g_rscale[rxn_sub[e]]), __float_as_int(sc));
}

// ---------------- L7: contributions + tail re-zero for next replay ------------
__global__ void k_contrib(const int* __restrict__ met_sub,
                          const int* __restrict__ rxn_sub,
                          const float* __restrict__ sto_sub,
                          const int* __restrict__ met_prod,
                          const int* __restrict__ rxn_prod,
                          const float* __restrict__ sto_prod,
                          float* __restrict__ out)
{
    int blk = blockIdx.x, tid = threadIdx.x;
    if (blk < CONTRIB_B) {
        int i = blk * 256 + tid;
        if (i >= E_SUB + E_PROD) return;
        int m, r; float sto;
        if (i < E_SUB) {
            m = met_sub[i];  r = rxn_sub[i];  sto = -sto_sub[i];
        } else {
            int e = i - E_SUB;
            m = met_prod[e]; r = rxn_prod[e]; sto = sto_prod[e];
        }
        atomicAdd(&out[m], sto * g_v[r] * g_rscale[r]);
    } else {
        // restore zero-state invariant for the next invocation
        int i = (blk - CONTRIB_B) * 256 + tid;
        int stride = (gridDim.x - CONTRIB_B) * 256;
        for (int p = i; p < N_RXN; p += stride) g_cnt[p] = 0;
        for (int p = i; p < NB1; p += stride) g_sstate[p] = 0ULL;
    }
}

// ---------------- launch ------------------------------------------------------
extern "C" void kernel_launch(void* const* d_in, const int* in_sizes, int n_in,
                              void* d_out, int out_size)
{
    const float* x        = (const float*)d_in[0];
    const int*   met_sub  = (const int*)  d_in[1];
    const int*   rxn_sub  = (const int*)  d_in[2];
    const float* sto_sub  = (const float*)d_in[3];
    const int*   met_prod = (const int*)  d_in[4];
    const int*   rxn_prod = (const int*)  d_in[5];
    const float* sto_prod = (const float*)d_in[6];
    const float* W1       = (const float*)d_in[7];
    const float* b1       = (const float*)d_in[8];
    const float* W2       = (const float*)d_in[9];
    const float* b2       = (const float*)d_in[10];
    const float* V1       = (const float*)d_in[11];
    const float* c1       = (const float*)d_in[12];
    const float* V2       = (const float*)d_in[13];
    const float* c2       = (const float*)d_in[14];
    const float* log_k    = (const float*)d_in[15];
    float* out = (float*)d_out;

    cudaFuncSetAttribute(k2_gemm, cudaFuncAttributeMaxDynamicSharedMemorySize,
                         K2_SMEM_BYTES);

    // 1: histogram + weight fold + zero(out, totcons)
    k_hist_init<<<HIST_B + HIDDEN + 1 + 256, 256>>>(rxn_sub, W2, V1, b2, out);
    // 2: single-pass scan -> g_start, g_cursor
    k_scan_lb<<<NB1, SCAN_BS>>>();
    // 3: CSR scatter
    k_scatter<<<(E_SUB + 255) / 256, 256>>>(rxn_sub);
    // 4: the big fused kernel (profiled slot)
    k2_gemm<<<K2_GRID, K2_THREADS, K2_SMEM_BYTES>>>(x, met_sub, sto_sub,
                                                    W1, b1, c1, V2, c2, log_k);
    // 5-7: limiting scale + output
    k_totcons<<<(E_SUB + 255) / 256, 256>>>(met_sub, rxn_sub, sto_sub);
    k_rscale<<<(E_SUB + 255) / 256, 256>>>(x, met_sub, rxn_sub);
    k_contrib<<<CONTRIB_B + 128, 256>>>(met_sub, rxn_sub, sto_sub,
                                        met_prod, rxn_prod, sto_prod, out);
}